// round 12
// baseline (speedup 1.0000x reference)
#include <cuda_runtime.h>

#define D_TOT 65536
#define S_TOT 1024
#define TS    32
#define NT    (S_TOT / TS)    // 32 tiles
#define PADW  (TS + 4)        // 36 floats: keeps cp.async rows 16B-aligned
#define NBLK  (D_TOT / 32)    // 2048 blocks
#define EPS   0.02f           // |bundled| below this -> precise-trig recompute

__device__ float        g_part[NBLK];
__device__ unsigned int g_ctr;   // zero at load; reset by the reducing block each call

// Direct-store design: cp.async stages weight/bias tiles (d-major, coalesced)
// into a 3-buffer smem ring, depth-2 ahead. Consume phase reads the staging
// buffer TRANSPOSED (lane tx -> d-column d0+tx), computes enc, and stores
// hvs coalesced -- no enc tile, no STS phase, one barrier per tile, and no
// LDG scoreboard stalls in the consume path. 3-buffer rotation makes
// stage-after-consume safe: stage(t+2) into buf[(t+2)%3] in iter t can only
// collide with consume(t') of the same buf at t'=t-1, and BAR(t) separates them.
__global__ __launch_bounds__(256, 6) void reghd_main(
    const float* __restrict__ x,
    const float* __restrict__ weight,
    const float* __restrict__ bias,
    const float* __restrict__ alpha,
    const float* __restrict__ M,
    float* __restrict__ out)   // [0]=model_result, [1..D]=q, [1+D ...]=hvs (SIZE,D)
{
    __shared__ float ws[3][32][PADW];   // staged weight, 13.8KB
    __shared__ float bs[3][32][PADW];   // staged bias
    __shared__ float sx[S_TOT];
    __shared__ float sa[S_TOT];
    __shared__ float bpart[8][32];
    __shared__ float red[256];
    __shared__ bool  is_last;

    const int tx  = threadIdx.x;              // 0..31 -> output d-column
    const int ty  = threadIdx.y;              // 0..7 (warp id)
    const int tid = ty * 32 + tx;
    const int d0  = blockIdx.x * 32;

    ((float4*)sx)[tid] = ((const float4*)x)[tid];
    ((float4*)sa)[tid] = ((const float4*)alpha)[tid];

    // Staging role: warp ty stages rows 4ty..4ty+3; lane -> (row, 16B chunk).
    const int srow = 4 * ty + (tx >> 3);
    const int scol = 4 * (tx & 7);
    const float* wsrc = weight + (size_t)(d0 + srow) * S_TOT + scol;
    const float* bsrc = bias   + (size_t)(d0 + srow) * S_TOT + scol;
    const unsigned wdst0 = (unsigned)__cvta_generic_to_shared(&ws[0][srow][scol]);
    const unsigned bdst0 = (unsigned)__cvta_generic_to_shared(&bs[0][srow][scol]);
    const unsigned BUFB  = 32 * PADW * 4;     // bytes per buffer

    // Prologue: stage tiles 0 and 1 (groups 0, 1).
    #pragma unroll
    for (int t = 0; t < 2; t++) {
        asm volatile("cp.async.cg.shared.global [%0], [%1], 16;\n"
                     "cp.async.cg.shared.global [%2], [%3], 16;\n"
                     "cp.async.commit_group;"
                     :: "r"(wdst0 + t * BUFB), "l"(wsrc + (size_t)t * TS),
                        "r"(bdst0 + t * BUFB), "l"(bsrc + (size_t)t * TS) : "memory");
    }

    float acc = 0.f;                           // bundled partial: d=tx, s in {ty+8k}
    float* __restrict__ hvs = out + 1 + D_TOT;

    for (int t = 0; t < NT; t++) {
        if (t < NT - 1) asm volatile("cp.async.wait_group 1;" ::: "memory");
        else            asm volatile("cp.async.wait_group 0;" ::: "memory");
        __syncthreads();   // publish staged tile t; fence prior consumes

        const int bsel = t % 3;
        const int s0   = t * TS;

        #pragma unroll
        for (int k = 0; k < 4; k++) {
            const int   sl = ty + 8 * k;
            const float wv = ws[bsel][tx][sl];       // transposed smem read
            const float bv = bs[bsel][tx][sl];
            const float p  = sx[s0 + sl] * wv;
            const float e  = __cosf(p + bv) * __sinf(p);
            __stcs(&hvs[(size_t)(s0 + sl) * D_TOT + (size_t)(d0 + tx)], e);
            acc = fmaf(e, sa[s0 + sl], acc);
        }

        if (t + 2 < NT) {   // stage tile t+2 into buf[(t+2)%3]
            const unsigned off = (unsigned)((t + 2) % 3) * BUFB;
            asm volatile("cp.async.cg.shared.global [%0], [%1], 16;\n"
                         "cp.async.cg.shared.global [%2], [%3], 16;\n"
                         "cp.async.commit_group;"
                         :: "r"(wdst0 + off), "l"(wsrc + (size_t)(t + 2) * TS),
                            "r"(bdst0 + off), "l"(bsrc + (size_t)(t + 2) * TS) : "memory");
        }
    }

    bpart[ty][tx] = acc;
    __syncthreads();

    // Warp 0: combine warp partials, guarded sign, q, dot(q,M) partial.
    if (ty == 0) {
        float v = 0.f;
        #pragma unroll
        for (int j = 0; j < 8; j++) v += bpart[j][tx];

        // Ballot-driven precise fallback: warp-uniform loop, full-mask legal.
        unsigned flag = __ballot_sync(0xFFFFFFFFu, fabsf(v) < EPS);
        while (flag) {
            const int r = __ffs(flag) - 1;
            flag &= flag - 1;
            const int d = d0 + r;
            float s2 = 0.f;
            for (int s = tx; s < S_TOT; s += 32) {
                const float wv = weight[(size_t)d * S_TOT + s];
                const float bv = bias[(size_t)d * S_TOT + s];
                const float pp = sx[s] * wv;
                s2 += cosf(pp + bv) * sinf(pp) * sa[s];
            }
            #pragma unroll
            for (int off = 16; off > 0; off >>= 1)
                s2 += __shfl_xor_sync(0xFFFFFFFFu, s2, off);
            if (tx == r) v = s2;
        }

        const float q = (v > 0.f) ? 1.f : -1.f;
        out[1 + d0 + tx] = q;
        float qm = q * M[d0 + tx];
        #pragma unroll
        for (int off = 16; off > 0; off >>= 1)
            qm += __shfl_xor_sync(0xFFFFFFFFu, qm, off);
        if (tx == 0) {
            g_part[blockIdx.x] = qm;
            __threadfence();
            const unsigned int prev = atomicAdd(&g_ctr, 1u);
            is_last = (prev == NBLK - 1);
        }
    }
    __syncthreads();

    // Last-arriving block reduces all partials (fixed order -> deterministic).
    if (is_last) {
        float s = 0.f;
        for (int i = tid; i < NBLK; i += 256)
            s += g_part[i];
        red[tid] = s;
        __syncthreads();
        #pragma unroll
        for (int k = 128; k > 0; k >>= 1) {
            if (tid < k) red[tid] += red[tid + k];
            __syncthreads();
        }
        if (tid == 0) {
            out[0] = red[0];
            g_ctr  = 0;          // reset for next graph replay
        }
    }
}

extern "C" void kernel_launch(void* const* d_in, const int* in_sizes, int n_in,
                              void* d_out, int out_size) {
    const float* x      = (const float*)d_in[0];
    const float* weight = (const float*)d_in[1];
    const float* bias   = (const float*)d_in[2];
    const float* alpha  = (const float*)d_in[3];
    const float* M      = (const float*)d_in[4];
    float* out = (float*)d_out;

    dim3 blk(32, 8);
    reghd_main<<<NBLK, blk>>>(x, weight, bias, alpha, M, out);
}